// round 11
// baseline (speedup 1.0000x reference)
#include <cuda_runtime.h>
#include <cuda_fp16.h>
#include <math.h>
#include <stdint.h>

// Problem constants
#define BB   512
#define NFG_ 1024
#define NFR_ 256
#define MROWS 32768
#define OUT_OFF ((size_t)MROWS * NFG_)

// Scratch (__device__ globals: alloc-free rule)
__device__ __half g_Ahi[(size_t)MROWS * NFG_];
__device__ __half g_Alo[(size_t)MROWS * NFG_];
__device__ __half g_Wc_hi[512 * NFG_];          // [W_theta^T ; W_phi^T]
__device__ __half g_Wc_lo[512 * NFG_];
__device__ __half g_Wg_hi[(size_t)NFG_ * NFG_];
__device__ __half g_Wg_lo[(size_t)NFG_ * NFG_]; // written, unused (kept simple)
__device__ __half g_TPh[(size_t)MROWS * 512];   // [theta|phi] fp16 hi
__device__ __half g_TPl[(size_t)MROWS * 512];
__device__ __half g_Gh[(size_t)MROWS * NFG_];   // G = feats@W_gcn (hi only)
__device__ __half g_Rh[(size_t)MROWS * 64];
__device__ __half g_Rl[(size_t)MROWS * 64];

// ---------------------------------------------------------------------------
// PTX helpers (sm_80-class: valid on plain sm_103 target)
// ---------------------------------------------------------------------------
__device__ __forceinline__ uint32_t smem_u32(const void* p) {
    uint32_t a;
    asm("{ .reg .u64 t; cvta.to.shared.u64 t, %1; cvt.u32.u64 %0, t; }"
        : "=r"(a) : "l"(p));
    return a;
}
__device__ __forceinline__ void cpa16(uint32_t dst, const void* src) {
    asm volatile("cp.async.cg.shared.global [%0], [%1], 16;"
                 :: "r"(dst), "l"(src));
}
__device__ __forceinline__ void cpa_commit() {
    asm volatile("cp.async.commit_group;" ::: "memory");
}
template <int N>
__device__ __forceinline__ void cpa_wait() {
    asm volatile("cp.async.wait_group %0;" :: "n"(N) : "memory");
}
__device__ __forceinline__ void ldsm4(uint32_t* r, uint32_t addr) {
    asm volatile("ldmatrix.sync.aligned.m8n8.x4.shared.b16 {%0,%1,%2,%3}, [%4];"
                 : "=r"(r[0]), "=r"(r[1]), "=r"(r[2]), "=r"(r[3]) : "r"(addr));
}
__device__ __forceinline__ void ldsm4t(uint32_t* r, uint32_t addr) {
    asm volatile("ldmatrix.sync.aligned.m8n8.x4.trans.shared.b16 {%0,%1,%2,%3}, [%4];"
                 : "=r"(r[0]), "=r"(r[1]), "=r"(r[2]), "=r"(r[3]) : "r"(addr));
}
__device__ __forceinline__ void mma16816(float* c, const uint32_t* a,
                                         uint32_t b0, uint32_t b1) {
    asm volatile(
        "mma.sync.aligned.m16n8k16.row.col.f32.f16.f16.f32 "
        "{%0,%1,%2,%3}, {%4,%5,%6,%7}, {%8,%9}, {%0,%1,%2,%3};"
        : "+f"(c[0]), "+f"(c[1]), "+f"(c[2]), "+f"(c[3])
        : "r"(a[0]), "r"(a[1]), "r"(a[2]), "r"(a[3]), "r"(b0), "r"(b1));
}

// ---------------------------------------------------------------------------
// feats split: x -> hi=f16(x), lo=f16(x-hi)
// ---------------------------------------------------------------------------
__global__ void split_feats(const float* __restrict__ x, __half* __restrict__ hi,
                            __half* __restrict__ lo, int n4)
{
    int i = blockIdx.x * blockDim.x + threadIdx.x;
    if (i >= n4) return;
    float4 v = ((const float4*)x)[i];
    __half h0 = __float2half_rn(v.x), h1 = __float2half_rn(v.y);
    __half h2 = __float2half_rn(v.z), h3 = __float2half_rn(v.w);
    __half l0 = __float2half_rn(v.x - __half2float(h0));
    __half l1 = __float2half_rn(v.y - __half2float(h1));
    __half l2 = __float2half_rn(v.z - __half2float(h2));
    __half l3 = __float2half_rn(v.w - __half2float(h3));
    ((__half2*)hi)[2 * i]     = __halves2half2(h0, h1);
    ((__half2*)hi)[2 * i + 1] = __halves2half2(h2, h3);
    ((__half2*)lo)[2 * i]     = __halves2half2(l0, l1);
    ((__half2*)lo)[2 * i + 1] = __halves2half2(l2, l3);
}

// ---------------------------------------------------------------------------
// Weight transpose + split: W[K,N] fp32 -> WT_hi/lo[N,K] fp16
// z-dim selects among up to 2 weight matrices written into one buffer.
// ---------------------------------------------------------------------------
__global__ void split_wt2(const float* __restrict__ W0, const float* __restrict__ W1,
                          __half* __restrict__ hi, __half* __restrict__ lo,
                          int K, int N)
{
    __shared__ float t[32][33];
    const float* W = (blockIdx.z == 0) ? W0 : W1;
    __half* hid = hi + (size_t)blockIdx.z * N * K;
    __half* lod = lo + (size_t)blockIdx.z * N * K;
    const int n0 = blockIdx.x << 5, k0 = blockIdx.y << 5;
#pragma unroll
    for (int i = threadIdx.y; i < 32; i += 8)
        t[i][threadIdx.x] = W[(size_t)(k0 + i) * N + n0 + threadIdx.x];
    __syncthreads();
#pragma unroll
    for (int i = threadIdx.y; i < 32; i += 8) {
        float v = t[threadIdx.x][i];
        __half h = __float2half_rn(v);
        hid[(size_t)(n0 + i) * K + k0 + threadIdx.x] = h;
        lod[(size_t)(n0 + i) * K + k0 + threadIdx.x] =
            __float2half_rn(v - __half2float(h));
    }
}

// ---------------------------------------------------------------------------
// Wide fp16 mma.sync GEMM: block tile 128x256, BK=32, 8 warps (4m x 2n),
// warp tile 32x128. SPLIT: C = Ah*Bh + Ah*Bl + Al*Bh  else  C = Ah*Bh.
// NSTAGE-deep cp.async pipeline. Output fp16 hi (+lo if WLO).
// Bias: col<256 -> bias0 else bias1.
// ---------------------------------------------------------------------------
#define WTILE_A 10240   // 128 rows x 80B
#define WTILE_B 20480   // 256 rows x 80B

template <bool SPLIT, bool BIAS, bool WLO, int NSTAGE>
__global__ __launch_bounds__(256, 1)
void gemm_w(const __half* __restrict__ Ah, const __half* __restrict__ Al,
            const __half* __restrict__ Bh, const __half* __restrict__ Bl,
            const float* __restrict__ bias0, const float* __restrict__ bias1,
            __half* __restrict__ Chi, __half* __restrict__ Clo,
            int M, int N, int K)
{
    extern __shared__ __align__(16) char sm[];
    const uint32_t sb = smem_u32(sm);
    const uint32_t aSz = (SPLIT ? 2 : 1) * WTILE_A;
    const uint32_t PS  = aSz + (SPLIT ? 2 : 1) * WTILE_B;

    const int tid  = threadIdx.x;
    const int wid  = tid >> 5, lane = tid & 31;
    const int wm   = wid & 3,  wn   = wid >> 2;
    const int g    = lane >> 2, tig = lane & 3;
    const int row0 = blockIdx.y << 7;
    const int col0 = blockIdx.x << 8;

    const int ra    = tid >> 1;
    const int cbase = (tid & 1) << 4;
    const uint32_t dst_l = (uint32_t)ra * 80u + ((uint32_t)(tid & 1) << 5);

    const int t8 = lane >> 3, r8 = lane & 7;
    uint32_t aoff[2];
#pragma unroll
    for (int mi = 0; mi < 2; mi++) {
        int arow = wm * 32 + mi * 16 + (t8 & 1) * 8 + r8;
        aoff[mi] = (uint32_t)(arow * 40 + (t8 >> 1) * 8) * 2u;
    }
    uint32_t boff[8];
#pragma unroll
    for (int j = 0; j < 8; j++) {
        int nrow = wn * 128 + (2 * j + (t8 >> 1)) * 8 + r8;
        boff[j] = (uint32_t)(nrow * 40 + (t8 & 1) * 8) * 2u;
    }

    const int nt = K >> 5;

    float acc[2][16][4];
#pragma unroll
    for (int mi = 0; mi < 2; mi++)
#pragma unroll
        for (int ni = 0; ni < 16; ni++)
#pragma unroll
            for (int q = 0; q < 4; q++) acc[mi][ni][q] = 0.0f;

    auto issue = [&](int t, int stage) {
        const int koff = t << 5;
        const uint32_t base = sb + (uint32_t)stage * PS;
        // A: 128 rows x 32 halves
        const __half* ash = Ah + (size_t)(row0 + ra) * K + koff + cbase;
        cpa16(base + dst_l, ash);
        cpa16(base + dst_l + 16, ash + 8);
        if (SPLIT) {
            const __half* asl = Al + (size_t)(row0 + ra) * K + koff + cbase;
            cpa16(base + WTILE_A + dst_l, asl);
            cpa16(base + WTILE_A + dst_l + 16, asl + 8);
        }
        // B: 256 rows x 32 halves
        const uint32_t bb = base + aSz;
#pragma unroll
        for (int h = 0; h < 2; h++) {
            const int row = ra + h * 128;
            const uint32_t dl = (uint32_t)row * 80u + ((uint32_t)(tid & 1) << 5);
            const __half* bsh = Bh + (size_t)(col0 + row) * K + koff + cbase;
            cpa16(bb + dl, bsh);
            cpa16(bb + dl + 16, bsh + 8);
            if (SPLIT) {
                const __half* bsl = Bl + (size_t)(col0 + row) * K + koff + cbase;
                cpa16(bb + WTILE_B + dl, bsl);
                cpa16(bb + WTILE_B + dl + 16, bsl + 8);
            }
        }
        cpa_commit();
    };

#pragma unroll
    for (int s = 0; s < NSTAGE - 1; s++) issue(s, s);

    for (int t = 0; t < nt; t++) {
        cpa_wait<NSTAGE - 2>();
        __syncthreads();
        const int nxt = t + NSTAGE - 1;
        if (nxt < nt) issue(nxt, nxt % NSTAGE);

        const uint32_t base = sb + (uint32_t)(t % NSTAGE) * PS;
        const uint32_t sAh = base;
        const uint32_t sAl = base + WTILE_A;
        const uint32_t sBh = base + aSz;
        const uint32_t sBl = base + aSz + WTILE_B;

#pragma unroll
        for (int ks = 0; ks < 2; ks++) {
            uint32_t ah[2][4], al[2][4];
#pragma unroll
            for (int mi = 0; mi < 2; mi++) {
                ldsm4(ah[mi], sAh + aoff[mi] + ks * 32);
                if (SPLIT) ldsm4(al[mi], sAl + aoff[mi] + ks * 32);
            }
#pragma unroll
            for (int j = 0; j < 8; j++) {
                uint32_t qh[4], ql[4];
                ldsm4(qh, sBh + boff[j] + ks * 32);
                if (SPLIT) ldsm4(ql, sBl + boff[j] + ks * 32);
#pragma unroll
                for (int nb = 0; nb < 2; nb++) {
                    const int ni = 2 * j + nb;
#pragma unroll
                    for (int mi = 0; mi < 2; mi++) {
                        mma16816(acc[mi][ni], ah[mi], qh[2 * nb], qh[2 * nb + 1]);
                        if (SPLIT) {
                            mma16816(acc[mi][ni], ah[mi], ql[2 * nb], ql[2 * nb + 1]);
                            mma16816(acc[mi][ni], al[mi], qh[2 * nb], qh[2 * nb + 1]);
                        }
                    }
                }
            }
        }
        __syncthreads();
    }

    // Epilogue
#pragma unroll
    for (int mi = 0; mi < 2; mi++) {
#pragma unroll
        for (int ni = 0; ni < 16; ni++) {
            const int r = row0 + wm * 32 + mi * 16 + g;
            const int c = col0 + wn * 128 + ni * 8 + tig * 2;
            float b0 = 0.0f, b1 = 0.0f;
            if (BIAS) {
                const float* bp = (c < 256) ? bias0 + c : bias1 + (c - 256);
                b0 = bp[0]; b1 = bp[1];
            }
#pragma unroll
            for (int h = 0; h < 2; h++) {
                const int rr = r + h * 8;
                float x0 = acc[mi][ni][2 * h] + b0;
                float x1 = acc[mi][ni][2 * h + 1] + b1;
                __half h0 = __float2half_rn(x0), h1 = __float2half_rn(x1);
                *(__half2*)(Chi + (size_t)rr * N + c) = __halves2half2(h0, h1);
                if (WLO) {
                    __half l0 = __float2half_rn(x0 - __half2float(h0));
                    __half l1 = __float2half_rn(x1 - __half2float(h1));
                    *(__half2*)(Clo + (size_t)rr * N + c) = __halves2half2(l0, l1);
                }
            }
        }
    }
}

// ---------------------------------------------------------------------------
// attn: sim = theta@phi^T/16 via split-fp16 MMA, mask, softmax -> R (fp32 +
// fp16 hi/lo). One block per batch. theta = TP cols 0-255, phi = cols 256-511.
// ---------------------------------------------------------------------------
#define AT_KP 136
#define AT_TH 0
#define AT_TL 17408
#define AT_PH 34816
#define AT_PL 52224
#define AT_SIM 69632
#define AT_CX 87040
#define AT_CY 87296
#define AT_SMEM 87552

__global__ __launch_bounds__(256, 2)
void attn_mma(const __half* __restrict__ TPh, const __half* __restrict__ TPl,
              const float* __restrict__ boxes, float* __restrict__ Rout,
              __half* __restrict__ Rhi, __half* __restrict__ Rlo)
{
    extern __shared__ __align__(16) char smc[];
    const uint32_t sb = smem_u32(smc);
    float* simb = (float*)(smc + AT_SIM);
    float* cx   = (float*)(smc + AT_CX);
    float* cy   = (float*)(smc + AT_CY);

    const int b   = blockIdx.x;
    const int tid = threadIdx.x;
    const int wid = tid >> 5, lane = tid & 31;
    const int wm  = wid & 3,  wn  = wid >> 2;
    const int g   = lane >> 2, tig = lane & 3;
    const int t8  = lane >> 3, r8  = lane & 7;

    if (tid < 64) {
        const float* bx = boxes + (size_t)b * 256 + tid * 4;
        cx[tid] = (bx[0] + bx[2]) * 0.5f;
        cy[tid] = (bx[1] + bx[3]) * 0.5f;
    }

    const uint32_t a_off =
        (uint32_t)((wm * 16 + (t8 & 1) * 8 + r8) * AT_KP + (t8 >> 1) * 8) * 2u;
    uint32_t b_off[2];
#pragma unroll
    for (int j = 0; j < 2; j++)
        b_off[j] = (uint32_t)((wn * 32 + (2 * j + (t8 >> 1)) * 8 + r8) * AT_KP +
                              (t8 & 1) * 8) * 2u;

    float acc[4][4];
#pragma unroll
    for (int ni = 0; ni < 4; ni++)
#pragma unroll
        for (int q = 0; q < 4; q++) acc[ni][q] = 0.0f;

    for (int kc = 0; kc < 2; kc++) {
#pragma unroll
        for (int i = 0; i < 4; i++) {
            const int u = tid + (i << 8);
            const int row = u >> 4, cu = u & 15;
            const size_t srow = ((size_t)b * 64 + row) * 512;
            const int colT = kc * 128 + cu * 8;
            const uint32_t dl = (uint32_t)(row * AT_KP + cu * 8) * 2u;
            cpa16(sb + AT_TH + dl, TPh + srow + colT);
            cpa16(sb + AT_TL + dl, TPl + srow + colT);
            cpa16(sb + AT_PH + dl, TPh + srow + 256 + colT);
            cpa16(sb + AT_PL + dl, TPl + srow + 256 + colT);
        }
        cpa_commit();
        cpa_wait<0>();
        __syncthreads();

#pragma unroll
        for (int ks = 0; ks < 8; ks++) {
            uint32_t ah[4], al[4];
            ldsm4(ah, sb + AT_TH + a_off + ks * 32);
            ldsm4(al, sb + AT_TL + a_off + ks * 32);
#pragma unroll
            for (int j = 0; j < 2; j++) {
                uint32_t qh[4], ql[4];
                ldsm4(qh, sb + AT_PH + b_off[j] + ks * 32);
                ldsm4(ql, sb + AT_PL + b_off[j] + ks * 32);
#pragma unroll
                for (int nb = 0; nb < 2; nb++) {
                    const int ni = 2 * j + nb;
                    mma16816(acc[ni], ah, qh[2 * nb], qh[2 * nb + 1]);
                    mma16816(acc[ni], ah, ql[2 * nb], ql[2 * nb + 1]);
                    mma16816(acc[ni], al, qh[2 * nb], qh[2 * nb + 1]);
                }
            }
        }
        __syncthreads();
    }

    // mask + store logits
    const float THR = 31.4f, NEG = __int_as_float(0xff800000);
#pragma unroll
    for (int ni = 0; ni < 4; ni++) {
        const int cm = wn * 32 + ni * 8 + tig * 2;
#pragma unroll
        for (int h = 0; h < 2; h++) {
            const int rn = wm * 16 + g + h * 8;
            const float cxr = cx[rn], cyr = cy[rn];
#pragma unroll
            for (int e = 0; e < 2; e++) {
                const int m = cm + e;
                float dx = cxr - cx[m], dy = cyr - cy[m];
                float d = sqrtf(dx * dx + dy * dy);
                simb[rn * 68 + m] = (d > THR) ? NEG : acc[ni][2 * h + e] * 0.0625f;
            }
        }
    }
    __syncthreads();

    // softmax: 4 threads per row
    {
        const int row = tid >> 2, q = tid & 3;
        float* sp = simb + row * 68 + q * 16;
        float v[16];
#pragma unroll
        for (int i = 0; i < 16; i += 4) {
            float4 t = *(float4*)(sp + i);
            v[i] = t.x; v[i + 1] = t.y; v[i + 2] = t.z; v[i + 3] = t.w;
        }
        float mx = v[0];
#pragma unroll
        for (int i = 1; i < 16; i++) mx = fmaxf(mx, v[i]);
        mx = fmaxf(mx, __shfl_xor_sync(0xffffffffu, mx, 1));
        mx = fmaxf(mx, __shfl_xor_sync(0xffffffffu, mx, 2));
        float s = 0.0f;
#pragma unroll
        for (int i = 0; i < 16; i++) { v[i] = __expf(v[i] - mx); s += v[i]; }
        s += __shfl_xor_sync(0xffffffffu, s, 1);
        s += __shfl_xor_sync(0xffffffffu, s, 2);
        const float inv = 1.0f / s;

        float* ro = Rout + (size_t)b * 4096 + row * 64 + q * 16;
        const size_t rbase = ((size_t)b * 64 + row) * 64 + q * 16;
#pragma unroll
        for (int i = 0; i < 16; i += 4) {
            float r0 = v[i] * inv, r1 = v[i + 1] * inv;
            float r2 = v[i + 2] * inv, r3 = v[i + 3] * inv;
            *(float4*)(ro + i) = make_float4(r0, r1, r2, r3);
            __half h0 = __float2half_rn(r0), h1 = __float2half_rn(r1);
            __half h2 = __float2half_rn(r2), h3 = __float2half_rn(r3);
            *(__half2*)(Rhi + rbase + i)     = __halves2half2(h0, h1);
            *(__half2*)(Rhi + rbase + i + 2) = __halves2half2(h2, h3);
            __half l0 = __float2half_rn(r0 - __half2float(h0));
            __half l1 = __float2half_rn(r1 - __half2float(h1));
            __half l2 = __float2half_rn(r2 - __half2float(h2));
            __half l3 = __float2half_rn(r3 - __half2float(h3));
            *(__half2*)(Rlo + rbase + i)     = __halves2half2(l0, l1);
            *(__half2*)(Rlo + rbase + i + 2) = __halves2half2(l2, l3);
        }
    }
}

// ---------------------------------------------------------------------------
// rg: out = relu((Rh+Rl) @ Gh) via 2-term fp16 MMA. Block: batch b x 256 cols.
// ---------------------------------------------------------------------------
#define RG_RP 72
#define RG_GP 264
#define RG_RH 0
#define RG_RL 9216
#define RG_GH 18432
#define RG_SMEM 52224

__global__ __launch_bounds__(256, 2)
void rg_mma(const __half* __restrict__ Rh, const __half* __restrict__ Rl,
            const __half* __restrict__ Gh, float* __restrict__ out)
{
    extern __shared__ __align__(16) char smc[];
    const uint32_t sb = smem_u32(smc);

    const int b   = blockIdx.y;
    const int cc  = blockIdx.x;
    const int tid = threadIdx.x;
    const int wid = tid >> 5, lane = tid & 31;
    const int wm  = wid & 3,  wn  = wid >> 2;
    const int g   = lane >> 2, tig = lane & 3;
    const int t8  = lane >> 3, r8  = lane & 7;

    // R tile 64x64 (hi+lo), G tile 64x256 (hi only)
#pragma unroll
    for (int i = 0; i < 2; i++) {
        const int u = tid + (i << 8);
        const int row = u >> 3, cu = u & 7;
        const size_t srow = ((size_t)b * 64 + row) * 64 + cu * 8;
        const uint32_t dl = (uint32_t)(row * RG_RP + cu * 8) * 2u;
        cpa16(sb + RG_RH + dl, Rh + srow);
        cpa16(sb + RG_RL + dl, Rl + srow);
    }
#pragma unroll
    for (int i = 0; i < 8; i++) {
        const int u = tid + (i << 8);
        const int row = u >> 5, cu = u & 31;
        const size_t srow = ((size_t)b * 64 + row) * 1024 + cc * 256 + cu * 8;
        const uint32_t dl = (uint32_t)(row * RG_GP + cu * 8) * 2u;
        cpa16(sb + RG_GH + dl, Gh + srow);
    }
    cpa_commit();
    cpa_wait<0>();
    __syncthreads();

    const uint32_t a_off =
        (uint32_t)((wm * 16 + (t8 & 1) * 8 + r8) * RG_RP + (t8 >> 1) * 8) * 2u;

    float acc[16][4];
#pragma unroll
    for (int ni = 0; ni < 16; ni++)
#pragma unroll
        for (int q = 0; q < 4; q++) acc[ni][q] = 0.0f;

#pragma unroll
    for (int ks = 0; ks < 4; ks++) {
        uint32_t ah[4], al[4];
        ldsm4(ah, sb + RG_RH + a_off + ks * 32);
        ldsm4(al, sb + RG_RL + a_off + ks * 32);
#pragma unroll
        for (int j = 0; j < 8; j++) {
            const uint32_t gl =
                (uint32_t)((ks * 16 + (lane & 15)) * RG_GP + wn * 128 + j * 16 +
                           (lane >> 4) * 8) * 2u;
            uint32_t qh[4];
            ldsm4t(qh, sb + RG_GH + gl);
#pragma unroll
            for (int nb = 0; nb < 2; nb++) {
                const int ni = 2 * j + nb;
                mma16816(acc[ni], ah, qh[2 * nb], qh[2 * nb + 1]);
                mma16816(acc[ni], al, qh[2 * nb], qh[2 * nb + 1]);
            }
        }
    }

    float* ob = out + (size_t)b * 65536 + cc * 256;
#pragma unroll
    for (int ni = 0; ni < 16; ni++) {
        const int r = wm * 16 + g;
        const int c = wn * 128 + ni * 8 + tig * 2;
        *(float2*)(ob + (size_t)r * 1024 + c) =
            make_float2(fmaxf(acc[ni][0], 0.0f), fmaxf(acc[ni][1], 0.0f));
        *(float2*)(ob + (size_t)(r + 8) * 1024 + c) =
            make_float2(fmaxf(acc[ni][2], 0.0f), fmaxf(acc[ni][3], 0.0f));
    }
}

// ---------------------------------------------------------------------------
extern "C" void kernel_launch(void* const* d_in, const int* in_sizes, int n_in,
                              void* d_out, int out_size)
{
    const float* feats   = (const float*)d_in[0];
    const float* boxes   = (const float*)d_in[1];
    const float* W_theta = (const float*)d_in[2];
    const float* b_theta = (const float*)d_in[3];
    const float* W_phi   = (const float*)d_in[4];
    const float* b_phi   = (const float*)d_in[5];
    const float* W_gcn   = (const float*)d_in[6];

    float* out = (float*)d_out;
    float* R   = out + OUT_OFF;

    __half *Ahi, *Alo, *wch, *wcl, *wgh, *wgl, *tph, *tpl, *gh, *rh, *rl;
    cudaGetSymbolAddress((void**)&Ahi, g_Ahi);
    cudaGetSymbolAddress((void**)&Alo, g_Alo);
    cudaGetSymbolAddress((void**)&wch, g_Wc_hi);
    cudaGetSymbolAddress((void**)&wcl, g_Wc_lo);
    cudaGetSymbolAddress((void**)&wgh, g_Wg_hi);
    cudaGetSymbolAddress((void**)&wgl, g_Wg_lo);
    cudaGetSymbolAddress((void**)&tph, g_TPh);
    cudaGetSymbolAddress((void**)&tpl, g_TPl);
    cudaGetSymbolAddress((void**)&gh,  g_Gh);
    cudaGetSymbolAddress((void**)&rh,  g_Rh);
    cudaGetSymbolAddress((void**)&rl,  g_Rl);

    // 1) operand conversion
    const int n4 = MROWS * NFG_ / 4;
    split_feats<<<n4 / 256, 256>>>(feats, Ahi, Alo, n4);
    split_wt2<<<dim3(8, 32, 2), dim3(32, 8)>>>(W_theta, W_phi, wch, wcl,
                                               NFG_, NFR_);
    split_wt2<<<dim3(32, 32, 1), dim3(32, 8)>>>(W_gcn, W_gcn, wgh, wgl,
                                                NFG_, NFG_);

    // 2) fused theta|phi projection: 3-term split, wide tile, 2 stages
    const int tp_smem = 2 * (2 * WTILE_A + 2 * WTILE_B);   // 122880
    cudaFuncSetAttribute(gemm_w<true, true, true, 2>,
                         cudaFuncAttributeMaxDynamicSharedMemorySize, tp_smem);
    gemm_w<true, true, true, 2><<<dim3(2, 256), 256, tp_smem>>>(
        Ahi, Alo, wch, wcl, b_theta, b_phi, tph, tpl, MROWS, 512, NFG_);

    // 3) G = feats @ W_gcn (single term), wide tile, 3 stages, hi-only output
    const int g_smem = 3 * (WTILE_A + WTILE_B);            // 92160
    cudaFuncSetAttribute(gemm_w<false, false, false, 3>,
                         cudaFuncAttributeMaxDynamicSharedMemorySize, g_smem);
    gemm_w<false, false, false, 3><<<dim3(4, 256), 256, g_smem>>>(
        Ahi, nullptr, wgh, nullptr, nullptr, nullptr, gh, nullptr,
        MROWS, NFG_, NFG_);

    // 4) attention + softmax -> relation_graph (+ fp16 hi/lo R)
    cudaFuncSetAttribute(attn_mma,
                         cudaFuncAttributeMaxDynamicSharedMemorySize, AT_SMEM);
    attn_mma<<<BB, 256, AT_SMEM>>>(tph, tpl, boxes, R, rh, rl);

    // 5) out = relu((Rh+Rl) @ Gh)
    cudaFuncSetAttribute(rg_mma,
                         cudaFuncAttributeMaxDynamicSharedMemorySize, RG_SMEM);
    rg_mma<<<dim3(4, BB), 256, RG_SMEM>>>(rh, rl, gh, out);
}

// round 13
// speedup vs baseline: 1.1542x; 1.1542x over previous
#include <cuda_runtime.h>
#include <cuda_fp16.h>
#include <math.h>
#include <stdint.h>

// Problem constants
#define BB   512
#define NFG_ 1024
#define NFR_ 256
#define MROWS 32768
#define OUT_OFF ((size_t)MROWS * NFG_)

// Scratch (__device__ globals: alloc-free rule)
__device__ __half g_Ahi[(size_t)MROWS * NFG_];
__device__ __half g_Alo[(size_t)MROWS * NFG_];
__device__ __half g_Wc_hi[512 * NFG_];          // [W_theta^T ; W_phi^T]
__device__ __half g_Wc_lo[512 * NFG_];
__device__ __half g_Wg_hi[(size_t)NFG_ * NFG_];
__device__ __half g_Wg_lo[(size_t)NFG_ * NFG_]; // written, unused
__device__ __half g_TPh[(size_t)MROWS * 512];   // [theta|phi] fp16 hi
__device__ __half g_TPl[(size_t)MROWS * 512];
__device__ __half g_Gh[(size_t)MROWS * NFG_];   // G = feats@W_gcn (hi only)
__device__ __half g_Rh[(size_t)MROWS * 64];
__device__ __half g_Rl[(size_t)MROWS * 64];

// ---------------------------------------------------------------------------
// PTX helpers (sm_80-class: valid on plain sm_103 target)
// ---------------------------------------------------------------------------
__device__ __forceinline__ uint32_t smem_u32(const void* p) {
    uint32_t a;
    asm("{ .reg .u64 t; cvta.to.shared.u64 t, %1; cvt.u32.u64 %0, t; }"
        : "=r"(a) : "l"(p));
    return a;
}
__device__ __forceinline__ void cpa16(uint32_t dst, const void* src) {
    asm volatile("cp.async.cg.shared.global [%0], [%1], 16;"
                 :: "r"(dst), "l"(src));
}
__device__ __forceinline__ void cpa_commit() {
    asm volatile("cp.async.commit_group;" ::: "memory");
}
template <int N>
__device__ __forceinline__ void cpa_wait() {
    asm volatile("cp.async.wait_group %0;" :: "n"(N) : "memory");
}
__device__ __forceinline__ void ldsm4(uint32_t* r, uint32_t addr) {
    asm volatile("ldmatrix.sync.aligned.m8n8.x4.shared.b16 {%0,%1,%2,%3}, [%4];"
                 : "=r"(r[0]), "=r"(r[1]), "=r"(r[2]), "=r"(r[3]) : "r"(addr));
}
__device__ __forceinline__ void ldsm4t(uint32_t* r, uint32_t addr) {
    asm volatile("ldmatrix.sync.aligned.m8n8.x4.trans.shared.b16 {%0,%1,%2,%3}, [%4];"
                 : "=r"(r[0]), "=r"(r[1]), "=r"(r[2]), "=r"(r[3]) : "r"(addr));
}
__device__ __forceinline__ void mma16816(float* c, const uint32_t* a,
                                         uint32_t b0, uint32_t b1) {
    asm volatile(
        "mma.sync.aligned.m16n8k16.row.col.f32.f16.f16.f32 "
        "{%0,%1,%2,%3}, {%4,%5,%6,%7}, {%8,%9}, {%0,%1,%2,%3};"
        : "+f"(c[0]), "+f"(c[1]), "+f"(c[2]), "+f"(c[3])
        : "r"(a[0]), "r"(a[1]), "r"(a[2]), "r"(a[3]), "r"(b0), "r"(b1));
}

// ---------------------------------------------------------------------------
// feats split: x -> hi=f16(x), lo=f16(x-hi)
// ---------------------------------------------------------------------------
__global__ void split_feats(const float* __restrict__ x, __half* __restrict__ hi,
                            __half* __restrict__ lo, int n4)
{
    int i = blockIdx.x * blockDim.x + threadIdx.x;
    if (i >= n4) return;
    float4 v = ((const float4*)x)[i];
    __half h0 = __float2half_rn(v.x), h1 = __float2half_rn(v.y);
    __half h2 = __float2half_rn(v.z), h3 = __float2half_rn(v.w);
    __half l0 = __float2half_rn(v.x - __half2float(h0));
    __half l1 = __float2half_rn(v.y - __half2float(h1));
    __half l2 = __float2half_rn(v.z - __half2float(h2));
    __half l3 = __float2half_rn(v.w - __half2float(h3));
    ((__half2*)hi)[2 * i]     = __halves2half2(h0, h1);
    ((__half2*)hi)[2 * i + 1] = __halves2half2(h2, h3);
    ((__half2*)lo)[2 * i]     = __halves2half2(l0, l1);
    ((__half2*)lo)[2 * i + 1] = __halves2half2(l2, l3);
}

// ---------------------------------------------------------------------------
// Weight transpose + split: W[K,N] fp32 -> WT_hi/lo[N,K] fp16
// z-dim selects among up to 2 weight matrices written into one buffer.
// ---------------------------------------------------------------------------
__global__ void split_wt2(const float* __restrict__ W0, const float* __restrict__ W1,
                          __half* __restrict__ hi, __half* __restrict__ lo,
                          int K, int N)
{
    __shared__ float t[32][33];
    const float* W = (blockIdx.z == 0) ? W0 : W1;
    __half* hid = hi + (size_t)blockIdx.z * N * K;
    __half* lod = lo + (size_t)blockIdx.z * N * K;
    const int n0 = blockIdx.x << 5, k0 = blockIdx.y << 5;
#pragma unroll
    for (int i = threadIdx.y; i < 32; i += 8)
        t[i][threadIdx.x] = W[(size_t)(k0 + i) * N + n0 + threadIdx.x];
    __syncthreads();
#pragma unroll
    for (int i = threadIdx.y; i < 32; i += 8) {
        float v = t[threadIdx.x][i];
        __half h = __float2half_rn(v);
        hid[(size_t)(n0 + i) * K + k0 + threadIdx.x] = h;
        lod[(size_t)(n0 + i) * K + k0 + threadIdx.x] =
            __float2half_rn(v - __half2float(h));
    }
}

// ---------------------------------------------------------------------------
// fp16 mma.sync GEMM, single-pass multi-segment, 128x128 tile, BK=32,
// 8 warps (4m x 2n), NSTAGE cp.async pipeline, 2 CTAs/SM.
//   SPLIT: C = Ah*Bh + Ah*Bl + Al*Bh   else C = Ah*Bh
// Output fp16 hi (+lo if WLO). Bias: col<256 -> bias0 else bias1.
// ---------------------------------------------------------------------------
#define TILE_B 10240   // 128 rows x 80B
#define GSTR 40        // smem row stride in halves

template <bool SPLIT, bool BIAS, bool WLO, int NSTAGE>
__global__ __launch_bounds__(256, 2)
void gemm_h2(const __half* __restrict__ Ah, const __half* __restrict__ Al,
             const __half* __restrict__ Bh, const __half* __restrict__ Bl,
             const float* __restrict__ bias0, const float* __restrict__ bias1,
             __half* __restrict__ Chi, __half* __restrict__ Clo,
             int M, int N, int K)
{
    extern __shared__ __align__(16) char sm[];
    const uint32_t sb = smem_u32(sm);
    const uint32_t PS = (SPLIT ? 4 : 2) * TILE_B;

    const int tid  = threadIdx.x;
    const int wid  = tid >> 5, lane = tid & 31;
    const int wm   = wid & 3,  wn   = wid >> 2;
    const int g    = lane >> 2, tig = lane & 3;
    const int row0 = blockIdx.y << 7;
    const int col0 = blockIdx.x << 7;

    const int ra    = tid >> 1;
    const int cbase = (tid & 1) << 4;
    const uint32_t dst_l = (uint32_t)ra * 80u + ((uint32_t)(tid & 1) << 5);

    const int t8 = lane >> 3, r8 = lane & 7;
    uint32_t aoff[2];
#pragma unroll
    for (int mi = 0; mi < 2; mi++) {
        int arow = wm * 32 + mi * 16 + (t8 & 1) * 8 + r8;
        aoff[mi] = (uint32_t)(arow * GSTR + (t8 >> 1) * 8) * 2u;
    }
    uint32_t boff[4];
#pragma unroll
    for (int j = 0; j < 4; j++) {
        int nrow = wn * 64 + (2 * j + (t8 >> 1)) * 8 + r8;
        boff[j] = (uint32_t)(nrow * GSTR + (t8 & 1) * 8) * 2u;
    }

    const int nt = K >> 5;

    float acc[2][8][4];
#pragma unroll
    for (int mi = 0; mi < 2; mi++)
#pragma unroll
        for (int ni = 0; ni < 8; ni++)
#pragma unroll
            for (int q = 0; q < 4; q++) acc[mi][ni][q] = 0.0f;

    auto issue = [&](int t, int stage) {
        const int koff = t << 5;
        const uint32_t base = sb + (uint32_t)stage * PS;
        const __half* ash = Ah + (size_t)(row0 + ra) * K + koff + cbase;
        cpa16(base + dst_l, ash);
        cpa16(base + dst_l + 16, ash + 8);
        const __half* bsh = Bh + (size_t)(col0 + ra) * K + koff + cbase;
        const uint32_t bbase = base + (SPLIT ? 2 : 1) * TILE_B;
        cpa16(bbase + dst_l, bsh);
        cpa16(bbase + dst_l + 16, bsh + 8);
        if (SPLIT) {
            const __half* asl = Al + (size_t)(row0 + ra) * K + koff + cbase;
            cpa16(base + TILE_B + dst_l, asl);
            cpa16(base + TILE_B + dst_l + 16, asl + 8);
            const __half* bsl = Bl + (size_t)(col0 + ra) * K + koff + cbase;
            cpa16(base + 3 * TILE_B + dst_l, bsl);
            cpa16(base + 3 * TILE_B + dst_l + 16, bsl + 8);
        }
        cpa_commit();
    };

#pragma unroll
    for (int s = 0; s < NSTAGE - 1; s++) issue(s, s);

    for (int t = 0; t < nt; t++) {
        cpa_wait<NSTAGE - 2>();
        __syncthreads();
        const int nxt = t + NSTAGE - 1;
        if (nxt < nt) issue(nxt, nxt % NSTAGE);

        const uint32_t base = sb + (uint32_t)(t % NSTAGE) * PS;
        const uint32_t sAh = base;
        const uint32_t sAl = base + TILE_B;
        const uint32_t sBh = base + (SPLIT ? 2 : 1) * TILE_B;
        const uint32_t sBl = base + 3 * TILE_B;

#pragma unroll
        for (int ks = 0; ks < 2; ks++) {
            uint32_t ah[2][4], al[2][4];
#pragma unroll
            for (int mi = 0; mi < 2; mi++) {
                ldsm4(ah[mi], sAh + aoff[mi] + ks * 32);
                if (SPLIT) ldsm4(al[mi], sAl + aoff[mi] + ks * 32);
            }
#pragma unroll
            for (int j = 0; j < 4; j++) {
                uint32_t qh[4], ql[4];
                ldsm4(qh, sBh + boff[j] + ks * 32);
                if (SPLIT) ldsm4(ql, sBl + boff[j] + ks * 32);
#pragma unroll
                for (int nb = 0; nb < 2; nb++) {
                    const int ni = 2 * j + nb;
#pragma unroll
                    for (int mi = 0; mi < 2; mi++) {
                        mma16816(acc[mi][ni], ah[mi], qh[2 * nb], qh[2 * nb + 1]);
                        if (SPLIT) {
                            mma16816(acc[mi][ni], ah[mi], ql[2 * nb], ql[2 * nb + 1]);
                            mma16816(acc[mi][ni], al[mi], qh[2 * nb], qh[2 * nb + 1]);
                        }
                    }
                }
            }
        }
    }

    // Epilogue: write fp16 hi (+lo)
#pragma unroll
    for (int mi = 0; mi < 2; mi++) {
#pragma unroll
        for (int ni = 0; ni < 8; ni++) {
            const int r = row0 + wm * 32 + mi * 16 + g;
            const int c = col0 + wn * 64 + ni * 8 + tig * 2;
            float b0 = 0.0f, b1 = 0.0f;
            if (BIAS) {
                const float* bp = (c < 256) ? bias0 + c : bias1 + (c - 256);
                b0 = bp[0]; b1 = bp[1];
            }
#pragma unroll
            for (int h = 0; h < 2; h++) {
                const int rr = r + h * 8;
                float x0 = acc[mi][ni][2 * h] + b0;
                float x1 = acc[mi][ni][2 * h + 1] + b1;
                __half h0 = __float2half_rn(x0), h1 = __float2half_rn(x1);
                *(__half2*)(Chi + (size_t)rr * N + c) = __halves2half2(h0, h1);
                if (WLO) {
                    __half l0 = __float2half_rn(x0 - __half2float(h0));
                    __half l1 = __float2half_rn(x1 - __half2float(h1));
                    *(__half2*)(Clo + (size_t)rr * N + c) = __halves2half2(l0, l1);
                }
            }
        }
    }
}

// ---------------------------------------------------------------------------
// attn: sim = theta@phi^T/16 via split-fp16 MMA, mask, softmax -> R (fp32 +
// fp16 hi/lo). One block per batch. theta = TP cols 0-255, phi = cols 256-511.
// ---------------------------------------------------------------------------
#define AT_KP 136
#define AT_TH 0
#define AT_TL 17408
#define AT_PH 34816
#define AT_PL 52224
#define AT_SIM 69632
#define AT_CX 87040
#define AT_CY 87296
#define AT_SMEM 87552

__global__ __launch_bounds__(256, 2)
void attn_mma(const __half* __restrict__ TPh, const __half* __restrict__ TPl,
              const float* __restrict__ boxes, float* __restrict__ Rout,
              __half* __restrict__ Rhi, __half* __restrict__ Rlo)
{
    extern __shared__ __align__(16) char smc[];
    const uint32_t sb = smem_u32(smc);
    float* simb = (float*)(smc + AT_SIM);
    float* cx   = (float*)(smc + AT_CX);
    float* cy   = (float*)(smc + AT_CY);

    const int b   = blockIdx.x;
    const int tid = threadIdx.x;
    const int wid = tid >> 5, lane = tid & 31;
    const int wm  = wid & 3,  wn  = wid >> 2;
    const int g   = lane >> 2, tig = lane & 3;
    const int t8  = lane >> 3, r8  = lane & 7;

    if (tid < 64) {
        const float* bx = boxes + (size_t)b * 256 + tid * 4;
        cx[tid] = (bx[0] + bx[2]) * 0.5f;
        cy[tid] = (bx[1] + bx[3]) * 0.5f;
    }

    const uint32_t a_off =
        (uint32_t)((wm * 16 + (t8 & 1) * 8 + r8) * AT_KP + (t8 >> 1) * 8) * 2u;
    uint32_t b_off[2];
#pragma unroll
    for (int j = 0; j < 2; j++)
        b_off[j] = (uint32_t)((wn * 32 + (2 * j + (t8 >> 1)) * 8 + r8) * AT_KP +
                              (t8 & 1) * 8) * 2u;

    float acc[4][4];
#pragma unroll
    for (int ni = 0; ni < 4; ni++)
#pragma unroll
        for (int q = 0; q < 4; q++) acc[ni][q] = 0.0f;

    for (int kc = 0; kc < 2; kc++) {
#pragma unroll
        for (int i = 0; i < 4; i++) {
            const int u = tid + (i << 8);
            const int row = u >> 4, cu = u & 15;
            const size_t srow = ((size_t)b * 64 + row) * 512;
            const int colT = kc * 128 + cu * 8;
            const uint32_t dl = (uint32_t)(row * AT_KP + cu * 8) * 2u;
            cpa16(sb + AT_TH + dl, TPh + srow + colT);
            cpa16(sb + AT_TL + dl, TPl + srow + colT);
            cpa16(sb + AT_PH + dl, TPh + srow + 256 + colT);
            cpa16(sb + AT_PL + dl, TPl + srow + 256 + colT);
        }
        cpa_commit();
        cpa_wait<0>();
        __syncthreads();

#pragma unroll
        for (int ks = 0; ks < 8; ks++) {
            uint32_t ah[4], al[4];
            ldsm4(ah, sb + AT_TH + a_off + ks * 32);
            ldsm4(al, sb + AT_TL + a_off + ks * 32);
#pragma unroll
            for (int j = 0; j < 2; j++) {
                uint32_t qh[4], ql[4];
                ldsm4(qh, sb + AT_PH + b_off[j] + ks * 32);
                ldsm4(ql, sb + AT_PL + b_off[j] + ks * 32);
#pragma unroll
                for (int nb = 0; nb < 2; nb++) {
                    const int ni = 2 * j + nb;
                    mma16816(acc[ni], ah, qh[2 * nb], qh[2 * nb + 1]);
                    mma16816(acc[ni], ah, ql[2 * nb], ql[2 * nb + 1]);
                    mma16816(acc[ni], al, qh[2 * nb], qh[2 * nb + 1]);
                }
            }
        }
        __syncthreads();
    }

    // mask + store logits
    const float THR = 31.4f, NEG = __int_as_float(0xff800000);
#pragma unroll
    for (int ni = 0; ni < 4; ni++) {
        const int cm = wn * 32 + ni * 8 + tig * 2;
#pragma unroll
        for (int h = 0; h < 2; h++) {
            const int rn = wm * 16 + g + h * 8;
            const float cxr = cx[rn], cyr = cy[rn];
#pragma unroll
            for (int e = 0; e < 2; e++) {
                const int m = cm + e;
                float dx = cxr - cx[m], dy = cyr - cy[m];
                float d = sqrtf(dx * dx + dy * dy);
                simb[rn * 68 + m] = (d > THR) ? NEG : acc[ni][2 * h + e] * 0.0625f;
            }
        }
    }
    __syncthreads();

    // softmax: 4 threads per row
    {
        const int row = tid >> 2, q = tid & 3;
        float* sp = simb + row * 68 + q * 16;
        float v[16];
#pragma unroll
        for (int i = 0; i < 16; i += 4) {
            float4 t = *(float4*)(sp + i);
            v[i] = t.x; v[i + 1] = t.y; v[i + 2] = t.z; v[i + 3] = t.w;
        }
        float mx = v[0];
#pragma unroll
        for (int i = 1; i < 16; i++) mx = fmaxf(mx, v[i]);
        mx = fmaxf(mx, __shfl_xor_sync(0xffffffffu, mx, 1));
        mx = fmaxf(mx, __shfl_xor_sync(0xffffffffu, mx, 2));
        float s = 0.0f;
#pragma unroll
        for (int i = 0; i < 16; i++) { v[i] = __expf(v[i] - mx); s += v[i]; }
        s += __shfl_xor_sync(0xffffffffu, s, 1);
        s += __shfl_xor_sync(0xffffffffu, s, 2);
        const float inv = 1.0f / s;

        float* ro = Rout + (size_t)b * 4096 + row * 64 + q * 16;
        const size_t rbase = ((size_t)b * 64 + row) * 64 + q * 16;
#pragma unroll
        for (int i = 0; i < 16; i += 4) {
            float r0 = v[i] * inv, r1 = v[i + 1] * inv;
            float r2 = v[i + 2] * inv, r3 = v[i + 3] * inv;
            *(float4*)(ro + i) = make_float4(r0, r1, r2, r3);
            __half h0 = __float2half_rn(r0), h1 = __float2half_rn(r1);
            __half h2 = __float2half_rn(r2), h3 = __float2half_rn(r3);
            *(__half2*)(Rhi + rbase + i)     = __halves2half2(h0, h1);
            *(__half2*)(Rhi + rbase + i + 2) = __halves2half2(h2, h3);
            __half l0 = __float2half_rn(r0 - __half2float(h0));
            __half l1 = __float2half_rn(r1 - __half2float(h1));
            __half l2 = __float2half_rn(r2 - __half2float(h2));
            __half l3 = __float2half_rn(r3 - __half2float(h3));
            *(__half2*)(Rlo + rbase + i)     = __halves2half2(l0, l1);
            *(__half2*)(Rlo + rbase + i + 2) = __halves2half2(l2, l3);
        }
    }
}

// ---------------------------------------------------------------------------
// rg: out = relu((Rh+Rl) @ Gh) via 2-term fp16 MMA. Block: batch b x 256 cols.
// ---------------------------------------------------------------------------
#define RG_RP 72
#define RG_GP 264
#define RG_RH 0
#define RG_RL 9216
#define RG_GH 18432
#define RG_SMEM 52224

__global__ __launch_bounds__(256, 2)
void rg_mma(const __half* __restrict__ Rh, const __half* __restrict__ Rl,
            const __half* __restrict__ Gh, float* __restrict__ out)
{
    extern __shared__ __align__(16) char smc[];
    const uint32_t sb = smem_u32(smc);

    const int b   = blockIdx.y;
    const int cc  = blockIdx.x;
    const int tid = threadIdx.x;
    const int wid = tid >> 5, lane = tid & 31;
    const int wm  = wid & 3,  wn  = wid >> 2;
    const int g   = lane >> 2, tig = lane & 3;
    const int t8  = lane >> 3, r8  = lane & 7;

    // R tile 64x64 (hi+lo), G tile 64x256 (hi only)
#pragma unroll
    for (int i = 0; i < 2; i++) {
        const int u = tid + (i << 8);
        const int row = u >> 3, cu = u & 7;
        const size_t srow = ((size_t)b * 64 + row) * 64 + cu * 8;
        const uint32_t dl = (uint32_t)(row * RG_RP + cu * 8) * 2u;
        cpa16(sb + RG_RH + dl, Rh + srow);
        cpa16(sb + RG_RL + dl, Rl + srow);
    }
#pragma unroll
    for (int i = 0; i < 8; i++) {
        const int u = tid + (i << 8);
        const int row = u >> 5, cu = u & 31;
        const size_t srow = ((size_t)b * 64 + row) * 1024 + cc * 256 + cu * 8;
        const uint32_t dl = (uint32_t)(row * RG_GP + cu * 8) * 2u;
        cpa16(sb + RG_GH + dl, Gh + srow);
    }
    cpa_commit();
    cpa_wait<0>();
    __syncthreads();

    const uint32_t a_off =
        (uint32_t)((wm * 16 + (t8 & 1) * 8 + r8) * RG_RP + (t8 >> 1) * 8) * 2u;

    float acc[16][4];
#pragma unroll
    for (int ni = 0; ni < 16; ni++)
#pragma unroll
        for (int q = 0; q < 4; q++) acc[ni][q] = 0.0f;

#pragma unroll
    for (int ks = 0; ks < 4; ks++) {
        uint32_t ah[4], al[4];
        ldsm4(ah, sb + RG_RH + a_off + ks * 32);
        ldsm4(al, sb + RG_RL + a_off + ks * 32);
#pragma unroll
        for (int j = 0; j < 8; j++) {
            const uint32_t gl =
                (uint32_t)((ks * 16 + (lane & 15)) * RG_GP + wn * 128 + j * 16 +
                           (lane >> 4) * 8) * 2u;
            uint32_t qh[4];
            ldsm4t(qh, sb + RG_GH + gl);
#pragma unroll
            for (int nb = 0; nb < 2; nb++) {
                const int ni = 2 * j + nb;
                mma16816(acc[ni], ah, qh[2 * nb], qh[2 * nb + 1]);
                mma16816(acc[ni], al, qh[2 * nb], qh[2 * nb + 1]);
            }
        }
    }

    float* ob = out + (size_t)b * 65536 + cc * 256;
#pragma unroll
    for (int ni = 0; ni < 16; ni++) {
        const int r = wm * 16 + g;
        const int c = wn * 128 + ni * 8 + tig * 2;
        *(float2*)(ob + (size_t)r * 1024 + c) =
            make_float2(fmaxf(acc[ni][0], 0.0f), fmaxf(acc[ni][1], 0.0f));
        *(float2*)(ob + (size_t)(r + 8) * 1024 + c) =
            make_float2(fmaxf(acc[ni][2], 0.0f), fmaxf(acc[ni][3], 0.0f));
    }
}

// ---------------------------------------------------------------------------
extern "C" void kernel_launch(void* const* d_in, const int* in_sizes, int n_in,
                              void* d_out, int out_size)
{
    const float* feats   = (const float*)d_in[0];
    const float* boxes   = (const float*)d_in[1];
    const float* W_theta = (const float*)d_in[2];
    const float* b_theta = (const float*)d_in[3];
    const float* W_phi   = (const float*)d_in[4];
    const float* b_phi   = (const float*)d_in[5];
    const float* W_gcn   = (const float*)d_in[6];

    float* out = (float*)d_out;
    float* R   = out + OUT_OFF;

    __half *Ahi, *Alo, *wch, *wcl, *wgh, *wgl, *tph, *tpl, *gh, *rh, *rl;
    cudaGetSymbolAddress((void**)&Ahi, g_Ahi);
    cudaGetSymbolAddress((void**)&Alo, g_Alo);
    cudaGetSymbolAddress((void**)&wch, g_Wc_hi);
    cudaGetSymbolAddress((void**)&wcl, g_Wc_lo);
    cudaGetSymbolAddress((void**)&wgh, g_Wg_hi);
    cudaGetSymbolAddress((void**)&wgl, g_Wg_lo);
    cudaGetSymbolAddress((void**)&tph, g_TPh);
    cudaGetSymbolAddress((void**)&tpl, g_TPl);
    cudaGetSymbolAddress((void**)&gh,  g_Gh);
    cudaGetSymbolAddress((void**)&rh,  g_Rh);
    cudaGetSymbolAddress((void**)&rl,  g_Rl);

    // 1) operand conversion
    const int n4 = MROWS * NFG_ / 4;
    split_feats<<<n4 / 256, 256>>>(feats, Ahi, Alo, n4);
    split_wt2<<<dim3(8, 32, 2), dim3(32, 8)>>>(W_theta, W_phi, wch, wcl,
                                               NFG_, NFR_);
    split_wt2<<<dim3(32, 32, 1), dim3(32, 8)>>>(W_gcn, W_gcn, wgh, wgl,
                                                NFG_, NFG_);

    // 2) fused theta|phi projection: 3-term split, 128x128 tile, 2 stages,
    //    2 CTAs/SM (80KB smem each)
    const int tp_smem = 2 * 4 * TILE_B;      // 81920
    cudaFuncSetAttribute(gemm_h2<true, true, true, 2>,
                         cudaFuncAttributeMaxDynamicSharedMemorySize, tp_smem);
    gemm_h2<true, true, true, 2><<<dim3(4, 256), 256, tp_smem>>>(
        Ahi, Alo, wch, wcl, b_theta, b_phi, tph, tpl, MROWS, 512, NFG_);

    // 3) G = feats @ W_gcn (single term), 4 stages, 2 CTAs/SM, hi-only out
    const int g_smem = 4 * 2 * TILE_B;       // 81920
    cudaFuncSetAttribute(gemm_h2<false, false, false, 4>,
                         cudaFuncAttributeMaxDynamicSharedMemorySize, g_smem);
    gemm_h2<false, false, false, 4><<<dim3(8, 256), 256, g_smem>>>(
        Ahi, nullptr, wgh, nullptr, nullptr, nullptr, gh, nullptr,
        MROWS, NFG_, NFG_);

    // 4) attention + softmax -> relation_graph (+ fp16 hi/lo R)
    cudaFuncSetAttribute(attn_mma,
                         cudaFuncAttributeMaxDynamicSharedMemorySize, AT_SMEM);
    attn_mma<<<BB, 256, AT_SMEM>>>(tph, tpl, boxes, R, rh, rl);

    // 5) out = relu((Rh+Rl) @ Gh)
    cudaFuncSetAttribute(rg_mma,
                         cudaFuncAttributeMaxDynamicSharedMemorySize, RG_SMEM);
    rg_mma<<<dim3(4, BB), 256, RG_SMEM>>>(rh, rl, gh, out);
}